// round 8
// baseline (speedup 1.0000x reference)
#include <cuda_runtime.h>
#include <cstdint>
#include <cstddef>

#define TT   2048
#define BB   64
#define SS   256
#define INK  64
#define DK   32
#define WK   (INK + DK)      // 96
#define CCH  64              // chunks
#define LCH  32              // chunk length (TT/CCH)
#define BT   32              // batch rows per CTA (pass1/pass3/drive)
#define NBT  (BB / BT)       // 2
#define TBS  (TT * BB * SS)  // 33,554,432
#define PAD  36              // smem row stride (floats), 144B (16B-aligned)

// ---------------- device scratch ----------------
__device__ float g_At[SS * SS];            // At[k][s] = A[s][k]
__device__ float g_Wt[WK * SS];            // Wt[i][s] = packed [Bw^T ; Ew^T]
__device__ float g_PA[SS * SS];            // power ping
__device__ float g_PB[SS * SS];            // power pong
__device__ float g_drive[TBS];             // drive[t,b,s]
__device__ float g_localEnd[(CCH - 1) * BB * SS];
__device__ float g_xstart[CCH * BB * SS];
__device__ unsigned g_sync;

// ---------------- packed f32x2 helpers ----------------
__device__ __forceinline__ void fma2(unsigned long long& acc,
                                     unsigned long long a, unsigned long long b) {
    asm("fma.rn.f32x2 %0, %1, %2, %0;" : "+l"(acc) : "l"(a), "l"(b));
}
__device__ __forceinline__ void add2(unsigned long long& acc, unsigned long long a) {
    asm("add.rn.f32x2 %0, %1, %0;" : "+l"(acc) : "l"(a));
}
__device__ __forceinline__ unsigned long long pack2(float lo, float hi) {
    unsigned long long r;
    asm("mov.b64 %0, {%1, %2};" : "=l"(r) : "f"(lo), "f"(hi));
    return r;
}
__device__ __forceinline__ float2 unpack2(unsigned long long v) {
    float2 f;
    asm("mov.b64 {%0, %1}, %2;" : "=f"(f.x), "=f"(f.y) : "l"(v));
    return f;
}

// ---------------- prep ----------------
__global__ void __launch_bounds__(256) k_prep(const float* __restrict__ A,
                                              const float* __restrict__ Bw,
                                              const float* __restrict__ Ew) {
    int idx = blockIdx.x * blockDim.x + threadIdx.x;
    if (idx == 0) g_sync = 0u;
    if (idx < SS * SS) {
        int k = idx / SS, s = idx % SS;
        g_At[idx] = A[s * SS + k];
    } else {
        int j = idx - SS * SS;
        if (j < WK * SS) {
            int i = j / SS, s = j % SS;
            g_Wt[j] = (i < INK) ? Bw[s * INK + i] : Ew[s * DK + (i - INK)];
        }
    }
}

// ======== GEMM core: 8 rows x 2 cols per thread (512-thread CTA) ========
// sx[k][PAD] state (broadcast LDS); roff = 8h; wbase = weights + s0 (LDG.64/k).
// acc0[q]/acc1[q] (q=0..3): rows (roff+2q, roff+2q+1) packed f32x2, cols s0/s0+1.
template <int KTILES>
__device__ __forceinline__ void gemm_q(const float (*sx)[PAD], int roff,
                                       const float* wbase,
                                       unsigned long long acc0[4],
                                       unsigned long long acc1[4]) {
    float2 wv[8];
#pragma unroll
    for (int i = 0; i < 8; ++i) wv[i] = *(const float2*)(wbase + (size_t)i * SS);

#pragma unroll 1
    for (int kt = 0; kt < KTILES; ++kt) {
        float2 wn[8];
        if (kt < KTILES - 1) {
#pragma unroll
            for (int i = 0; i < 8; ++i)
                wn[i] = *(const float2*)(wbase + (size_t)((kt + 1) * 8 + i) * SS);
        }
#pragma unroll
        for (int i = 0; i < 8; ++i) {
            const int k = kt * 8 + i;
            unsigned long long w0 = pack2(wv[i].x, wv[i].x);
            unsigned long long w1 = pack2(wv[i].y, wv[i].y);
            const ulonglong2* xv = (const ulonglong2*)(&sx[k][roff]);
            ulonglong2 v0 = xv[0], v1 = xv[1];   // rows roff..roff+7
            fma2(acc0[0], v0.x, w0); fma2(acc0[1], v0.y, w0);
            fma2(acc0[2], v1.x, w0); fma2(acc0[3], v1.y, w0);
            fma2(acc1[0], v0.x, w1); fma2(acc1[1], v0.y, w1);
            fma2(acc1[2], v1.x, w1); fma2(acc1[3], v1.y, w1);
        }
#pragma unroll
        for (int i = 0; i < 8; ++i) wv[i] = wn[i];
    }
}

// ---------------- drive: g_drive[t,b,s] = U@Bw^T + D@Ew^T ----------------
__global__ void __launch_bounds__(512) k_drive(const float* __restrict__ U,
                                               const float* __restrict__ D) {
    __shared__ __align__(16) float sRow[WK][PAD];
    const int R0   = blockIdx.x * 32;
    const int tid  = threadIdx.x;
    const int h    = tid >> 7;
    const int lane = tid & 127;
    const int s0   = 2 * lane;
    const int roff = 8 * h;

    for (int e = tid; e < 32 * WK; e += 512) {
        int r = e / WK, i = e % WK;
        size_t R = (size_t)(R0 + r);
        sRow[i][r] = (i < INK) ? U[R * INK + i] : D[R * DK + (i - INK)];
    }
    __syncthreads();

    unsigned long long acc0[4], acc1[4];
#pragma unroll
    for (int q = 0; q < 4; ++q) { acc0[q] = 0ull; acc1[q] = 0ull; }

    gemm_q<WK / 8>(sRow, roff, g_Wt + s0, acc0, acc1);

#pragma unroll
    for (int q = 0; q < 4; ++q) {
        float2 f0 = unpack2(acc0[q]);
        float2 f1 = unpack2(acc1[q]);
        *(float2*)(&g_drive[(size_t)(R0 + roff + 2 * q) * SS + s0])     = make_float2(f0.x, f1.x);
        *(float2*)(&g_drive[(size_t)(R0 + roff + 2 * q + 1) * SS + s0]) = make_float2(f0.y, f1.y);
    }
}

// ---------------- powers: (A^T)^32 via 5 fused squarings ----------------
__global__ void __launch_bounds__(256) k_powers() {
    __shared__ float sRow[2][SS];
    const int tid = threadIdx.x;
    const int k0  = blockIdx.x * 2;

    const float* src = g_At;
    float*       dst = g_PA;
#pragma unroll 1
    for (int step = 0; step < 5; ++step) {
        sRow[0][tid] = src[(size_t)k0 * SS + tid];
        sRow[1][tid] = src[(size_t)(k0 + 1) * SS + tid];
        __syncthreads();
        float a0 = 0.f, a1 = 0.f;
#pragma unroll 4
        for (int j = 0; j < SS; ++j) {
            float b = src[(size_t)j * SS + tid];
            a0 = fmaf(sRow[0][j], b, a0);
            a1 = fmaf(sRow[1][j], b, a1);
        }
        dst[(size_t)k0 * SS + tid]       = a0;
        dst[(size_t)(k0 + 1) * SS + tid] = a1;
        __syncthreads();
        if (tid == 0) {
            __threadfence();
            atomicAdd(&g_sync, 1u);
            unsigned target = 128u * (unsigned)(step + 1);
            while (*((volatile unsigned*)&g_sync) < target) { __nanosleep(64); }
        }
        __syncthreads();
        src = dst;
        dst = (dst == g_PA) ? g_PB : g_PA;
    }
}

// ---------------- pass1 ----------------
__global__ void __launch_bounds__(512) k_pass1() {
    const int c    = blockIdx.x / NBT;
    const int b0   = (blockIdx.x % NBT) * BT;
    const int tid  = threadIdx.x;
    const int h    = tid >> 7;
    const int lane = tid & 127;
    const int s0   = 2 * lane;
    const int roff = 8 * h;
    __shared__ __align__(16) float sx[2][SS][PAD];

    // j = 0: x1 = drive[t0]  (zero initial state)
    {
        const int t0 = c * LCH;
#pragma unroll
        for (int r = 0; r < 8; ++r) {
            float2 d = *(const float2*)(&g_drive[((size_t)t0 * BB + b0 + roff + r) * SS + s0]);
            sx[0][s0][roff + r]     = d.x;
            sx[0][s0 + 1][roff + r] = d.y;
        }
    }
    __syncthreads();

    int pb = 0;
#pragma unroll 1
    for (int j = 1; j < LCH; ++j) {
        const int t = c * LCH + j;

        // prefetch this step's drive BEFORE the gemm (DRAM latency overlap)
        const float* dr = g_drive + ((size_t)t * BB + b0 + roff) * SS + s0;
        float2 dv[8];
#pragma unroll
        for (int r = 0; r < 8; ++r) dv[r] = *(const float2*)(dr + (size_t)r * SS);

        unsigned long long acc0[4], acc1[4];
#pragma unroll
        for (int q = 0; q < 4; ++q) { acc0[q] = 0ull; acc1[q] = 0ull; }

        gemm_q<SS / 8>(sx[pb], roff, g_At + s0, acc0, acc1);

#pragma unroll
        for (int q = 0; q < 4; ++q) {
            add2(acc0[q], pack2(dv[2 * q].x, dv[2 * q + 1].x));
            add2(acc1[q], pack2(dv[2 * q].y, dv[2 * q + 1].y));
        }

        ulonglong2* q0 = (ulonglong2*)(&sx[1 - pb][s0][roff]);
        ulonglong2* q1 = (ulonglong2*)(&sx[1 - pb][s0 + 1][roff]);
        q0[0] = make_ulonglong2(acc0[0], acc0[1]);
        q0[1] = make_ulonglong2(acc0[2], acc0[3]);
        q1[0] = make_ulonglong2(acc1[0], acc1[1]);
        q1[1] = make_ulonglong2(acc1[2], acc1[3]);
        __syncthreads();
        pb = 1 - pb;
    }
#pragma unroll
    for (int r = 0; r < 8; ++r)
        *(float2*)(&g_localEnd[((size_t)c * BB + b0 + roff + r) * SS + s0]) =
            make_float2(sx[pb][s0][roff + r], sx[pb][s0 + 1][roff + r]);
}

// ---------------- pass2: boundary recurrence ----------------
__global__ void __launch_bounds__(128) k_pass2(const float* __restrict__ x0) {
    const int b0 = blockIdx.x * 2;   // 32 CTAs
    const int s0 = 2 * threadIdx.x;
    __shared__ __align__(8) float sxp[SS][2];   // [k][row]

    float2 vA = *(const float2*)(&x0[(size_t)b0 * SS + s0]);
    float2 vB = *(const float2*)(&x0[(size_t)(b0 + 1) * SS + s0]);
    sxp[s0][0] = vA.x;     sxp[s0][1] = vB.x;
    sxp[s0 + 1][0] = vA.y; sxp[s0 + 1][1] = vB.y;
    *(float2*)(&g_xstart[((size_t)b0) * SS + s0])       = vA;
    *(float2*)(&g_xstart[((size_t)(b0 + 1)) * SS + s0]) = vB;
    __syncthreads();

#pragma unroll 1
    for (int c = 1; c < CCH; ++c) {
        float2 eA = *(const float2*)(&g_localEnd[((size_t)(c - 1) * BB + b0) * SS + s0]);
        float2 eB = *(const float2*)(&g_localEnd[((size_t)(c - 1) * BB + b0 + 1) * SS + s0]);
        unsigned long long acc0[4], acc1[4];
#pragma unroll
        for (int u = 0; u < 4; ++u) { acc0[u] = 0ull; acc1[u] = 0ull; }
        const float* wp = g_PA + s0;   // (A^T)^32
#pragma unroll 2
        for (int k = 0; k < SS; k += 4) {
#pragma unroll
            for (int u = 0; u < 4; ++u) {
                float2 w = *(const float2*)(wp + (size_t)(k + u) * SS);
                unsigned long long xp = *(const unsigned long long*)(&sxp[k + u][0]);
                fma2(acc0[u], xp, pack2(w.x, w.x));
                fma2(acc1[u], xp, pack2(w.y, w.y));
            }
        }
        add2(acc0[0], acc0[1]); add2(acc0[2], acc0[3]); add2(acc0[0], acc0[2]);
        add2(acc1[0], acc1[1]); add2(acc1[2], acc1[3]); add2(acc1[0], acc1[2]);
        float2 f0 = unpack2(acc0[0]);
        float2 f1 = unpack2(acc1[0]);
        f0.x += eA.x; f0.y += eB.x;
        f1.x += eA.y; f1.y += eB.y;
        __syncthreads();
        sxp[s0][0] = f0.x;     sxp[s0][1] = f0.y;
        sxp[s0 + 1][0] = f1.x; sxp[s0 + 1][1] = f1.y;
        __syncthreads();
        *(float2*)(&g_xstart[((size_t)c * BB + b0) * SS + s0])     = make_float2(f0.x, f1.x);
        *(float2*)(&g_xstart[((size_t)c * BB + b0 + 1) * SS + s0]) = make_float2(f0.y, f1.y);
    }
}

// ---------------- pass3 ----------------
__global__ void __launch_bounds__(512) k_pass3(float* __restrict__ out, int dup) {
    const int c    = blockIdx.x / NBT;
    const int b0   = (blockIdx.x % NBT) * BT;
    const int tid  = threadIdx.x;
    const int h    = tid >> 7;
    const int lane = tid & 127;
    const int s0   = 2 * lane;
    const int roff = 8 * h;
    __shared__ __align__(16) float sx[2][SS][PAD];

#pragma unroll
    for (int r = 0; r < 8; ++r) {
        float2 v = *(const float2*)(&g_xstart[((size_t)c * BB + b0 + roff + r) * SS + s0]);
        sx[0][s0][roff + r]     = v.x;
        sx[0][s0 + 1][roff + r] = v.y;
    }
    __syncthreads();

    float* out2 = out + (size_t)TBS;
    int pb = 0;

#pragma unroll 1
    for (int j = 0; j < LCH; ++j) {
        const int t = c * LCH + j;

        const float* dr = g_drive + ((size_t)t * BB + b0 + roff) * SS + s0;
        float2 dv[8];
#pragma unroll
        for (int r = 0; r < 8; ++r) dv[r] = *(const float2*)(dr + (size_t)r * SS);

        unsigned long long acc0[4], acc1[4];
#pragma unroll
        for (int q = 0; q < 4; ++q) { acc0[q] = 0ull; acc1[q] = 0ull; }

        gemm_q<SS / 8>(sx[pb], roff, g_At + s0, acc0, acc1);

#pragma unroll
        for (int q = 0; q < 4; ++q) {
            add2(acc0[q], pack2(dv[2 * q].x, dv[2 * q + 1].x));
            add2(acc1[q], pack2(dv[2 * q].y, dv[2 * q + 1].y));
        }

        ulonglong2* q0 = (ulonglong2*)(&sx[1 - pb][s0][roff]);
        ulonglong2* q1 = (ulonglong2*)(&sx[1 - pb][s0 + 1][roff]);
        q0[0] = make_ulonglong2(acc0[0], acc0[1]);
        q0[1] = make_ulonglong2(acc0[2], acc0[3]);
        q1[0] = make_ulonglong2(acc1[0], acc1[1]);
        q1[1] = make_ulonglong2(acc1[2], acc1[3]);

        size_t obase = ((size_t)t * BB + b0 + roff) * SS + s0;
#pragma unroll
        for (int q = 0; q < 4; ++q) {
            float2 f0 = unpack2(acc0[q]);
            float2 f1 = unpack2(acc1[q]);
            float2 oA = make_float2(f0.x, f1.x);
            float2 oB = make_float2(f0.y, f1.y);
            size_t oa = obase + (size_t)(2 * q) * SS;
            size_t ob = obase + (size_t)(2 * q + 1) * SS;
            *(float2*)(&out[oa]) = oA;
            *(float2*)(&out[ob]) = oB;
            if (dup) {
                *(float2*)(&out2[oa]) = oA;
                *(float2*)(&out2[ob]) = oB;
            }
        }
        __syncthreads();
        pb = 1 - pb;
    }
}

// ---------------- launcher ----------------
extern "C" void kernel_launch(void* const* d_in, const int* in_sizes, int n_in,
                              void* d_out, int out_size) {
    const float* x  = (const float*)d_in[0];
    const float* U  = (const float*)d_in[1];
    const float* D  = (const float*)d_in[2];
    const float* Aw = (const float*)d_in[3];
    const float* Bw = (const float*)d_in[4];
    const float* Ew = (const float*)d_in[5];
    float* out = (float*)d_out;
    int dup = (out_size >= 2 * TBS) ? 1 : 0;

    k_prep<<<(SS * SS + WK * SS + 255) / 256, 256>>>(Aw, Bw, Ew);   // 0
    k_drive<<<(TT * BB) / 32, 512>>>(U, D);                          // 1
    k_powers<<<SS / 2, 256>>>();                                     // 2
    k_pass1<<<(CCH - 1) * NBT, 512>>>();                             // 3
    k_pass2<<<BB / 2, 128>>>(x);                                     // 4
    k_pass3<<<CCH * NBT, 512>>>(out, dup);                           // 5
}

// round 9
// speedup vs baseline: 1.0070x; 1.0070x over previous
#include <cuda_runtime.h>
#include <cstdint>
#include <cstddef>

#define TT   2048
#define BB   64
#define SS   256
#define INK  64
#define DK   32
#define WK   (INK + DK)      // 96
#define CCH  64              // chunks
#define LCH  32              // chunk length (TT/CCH)
#define BT   32              // batch rows per CTA (pass1/pass3/drive)
#define NBT  (BB / BT)       // 2
#define TBS  (TT * BB * SS)  // 33,554,432
#define PAD  36              // smem row stride (floats), 144B (16B-aligned)

// ---------------- device scratch ----------------
__device__ float g_At[SS * SS];            // At[k][s] = A[s][k]
__device__ float g_Wt[WK * SS];            // Wt[i][s] = packed [Bw^T ; Ew^T]
__device__ float g_PA[SS * SS];            // power ping
__device__ float g_PB[SS * SS];            // power pong
__device__ float g_drive[TBS];             // drive[t,b,s]
__device__ float g_localEnd[(CCH - 1) * BB * SS];
__device__ float g_xstart[CCH * BB * SS];
__device__ unsigned g_sync;

// ---------------- packed f32x2 helpers ----------------
__device__ __forceinline__ void fma2(unsigned long long& acc,
                                     unsigned long long a, unsigned long long b) {
    asm("fma.rn.f32x2 %0, %1, %2, %0;" : "+l"(acc) : "l"(a), "l"(b));
}
__device__ __forceinline__ void add2(unsigned long long& acc, unsigned long long a) {
    asm("add.rn.f32x2 %0, %1, %0;" : "+l"(acc) : "l"(a));
}
__device__ __forceinline__ unsigned long long pack2(float lo, float hi) {
    unsigned long long r;
    asm("mov.b64 %0, {%1, %2};" : "=l"(r) : "f"(lo), "f"(hi));
    return r;
}
__device__ __forceinline__ float2 unpack2(unsigned long long v) {
    float2 f;
    asm("mov.b64 {%0, %1}, %2;" : "=f"(f.x), "=f"(f.y) : "l"(v));
    return f;
}

// ---------------- prep ----------------
__global__ void __launch_bounds__(256) k_prep(const float* __restrict__ A,
                                              const float* __restrict__ Bw,
                                              const float* __restrict__ Ew) {
    int idx = blockIdx.x * blockDim.x + threadIdx.x;
    if (idx == 0) g_sync = 0u;
    if (idx < SS * SS) {
        int k = idx / SS, s = idx % SS;
        g_At[idx] = A[s * SS + k];
    } else {
        int j = idx - SS * SS;
        if (j < WK * SS) {
            int i = j / SS, s = j % SS;
            g_Wt[j] = (i < INK) ? Bw[s * INK + i] : Ew[s * DK + (i - INK)];
        }
    }
}

// ======== GEMM core: 8 rows x 2 cols per thread (512-thread CTA) ========
// sx[k][PAD] state (broadcast LDS); roff = 8h; wbase = weights + s0 (LDG.64/k).
// acc0[q]/acc1[q] (q=0..3): rows (roff+2q, roff+2q+1) packed f32x2, cols s0/s0+1.
template <int KTILES>
__device__ __forceinline__ void gemm_q(const float (*sx)[PAD], int roff,
                                       const float* wbase,
                                       unsigned long long acc0[4],
                                       unsigned long long acc1[4]) {
    float2 wv[8];
#pragma unroll
    for (int i = 0; i < 8; ++i) wv[i] = *(const float2*)(wbase + (size_t)i * SS);

#pragma unroll 1
    for (int kt = 0; kt < KTILES; ++kt) {
        float2 wn[8];
        if (kt < KTILES - 1) {
#pragma unroll
            for (int i = 0; i < 8; ++i)
                wn[i] = *(const float2*)(wbase + (size_t)((kt + 1) * 8 + i) * SS);
        }
#pragma unroll
        for (int i = 0; i < 8; ++i) {
            const int k = kt * 8 + i;
            unsigned long long w0 = pack2(wv[i].x, wv[i].x);
            unsigned long long w1 = pack2(wv[i].y, wv[i].y);
            const ulonglong2* xv = (const ulonglong2*)(&sx[k][roff]);
            ulonglong2 v0 = xv[0], v1 = xv[1];   // rows roff..roff+7
            fma2(acc0[0], v0.x, w0); fma2(acc0[1], v0.y, w0);
            fma2(acc0[2], v1.x, w0); fma2(acc0[3], v1.y, w0);
            fma2(acc1[0], v0.x, w1); fma2(acc1[1], v0.y, w1);
            fma2(acc1[2], v1.x, w1); fma2(acc1[3], v1.y, w1);
        }
#pragma unroll
        for (int i = 0; i < 8; ++i) wv[i] = wn[i];
    }
}

// ---------------- drive: g_drive[t,b,s] = U@Bw^T + D@Ew^T ----------------
__global__ void __launch_bounds__(512) k_drive(const float* __restrict__ U,
                                               const float* __restrict__ D) {
    __shared__ __align__(16) float sRow[WK][PAD];
    const int R0   = blockIdx.x * 32;
    const int tid  = threadIdx.x;
    const int h    = tid >> 7;
    const int lane = tid & 127;
    const int s0   = 2 * lane;
    const int roff = 8 * h;

    for (int e = tid; e < 32 * WK; e += 512) {
        int r = e / WK, i = e % WK;
        size_t R = (size_t)(R0 + r);
        sRow[i][r] = (i < INK) ? U[R * INK + i] : D[R * DK + (i - INK)];
    }
    __syncthreads();

    unsigned long long acc0[4], acc1[4];
#pragma unroll
    for (int q = 0; q < 4; ++q) { acc0[q] = 0ull; acc1[q] = 0ull; }

    gemm_q<WK / 8>(sRow, roff, g_Wt + s0, acc0, acc1);

#pragma unroll
    for (int q = 0; q < 4; ++q) {
        float2 f0 = unpack2(acc0[q]);
        float2 f1 = unpack2(acc1[q]);
        *(float2*)(&g_drive[(size_t)(R0 + roff + 2 * q) * SS + s0])     = make_float2(f0.x, f1.x);
        *(float2*)(&g_drive[(size_t)(R0 + roff + 2 * q + 1) * SS + s0]) = make_float2(f0.y, f1.y);
    }
}

// ---------------- powers: (A^T)^32 via 5 fused squarings ----------------
__global__ void __launch_bounds__(256) k_powers() {
    __shared__ float sRow[2][SS];
    const int tid = threadIdx.x;
    const int k0  = blockIdx.x * 2;

    const float* src = g_At;
    float*       dst = g_PA;
#pragma unroll 1
    for (int step = 0; step < 5; ++step) {
        sRow[0][tid] = src[(size_t)k0 * SS + tid];
        sRow[1][tid] = src[(size_t)(k0 + 1) * SS + tid];
        __syncthreads();
        float a0 = 0.f, a1 = 0.f;
#pragma unroll 4
        for (int j = 0; j < SS; ++j) {
            float b = src[(size_t)j * SS + tid];
            a0 = fmaf(sRow[0][j], b, a0);
            a1 = fmaf(sRow[1][j], b, a1);
        }
        dst[(size_t)k0 * SS + tid]       = a0;
        dst[(size_t)(k0 + 1) * SS + tid] = a1;
        __syncthreads();
        if (tid == 0) {
            __threadfence();
            atomicAdd(&g_sync, 1u);
            unsigned target = 128u * (unsigned)(step + 1);
            while (*((volatile unsigned*)&g_sync) < target) { __nanosleep(64); }
        }
        __syncthreads();
        src = dst;
        dst = (dst == g_PA) ? g_PB : g_PA;
    }
}

// ---------------- pass1 ----------------
__global__ void __launch_bounds__(512) k_pass1() {
    const int c    = blockIdx.x / NBT;
    const int b0   = (blockIdx.x % NBT) * BT;
    const int tid  = threadIdx.x;
    const int h    = tid >> 7;
    const int lane = tid & 127;
    const int s0   = 2 * lane;
    const int roff = 8 * h;
    __shared__ __align__(16) float sx[2][SS][PAD];

    // j = 0: x1 = drive[t0]  (zero initial state)
    {
        const int t0 = c * LCH;
#pragma unroll
        for (int r = 0; r < 8; ++r) {
            float2 d = *(const float2*)(&g_drive[((size_t)t0 * BB + b0 + roff + r) * SS + s0]);
            sx[0][s0][roff + r]     = d.x;
            sx[0][s0 + 1][roff + r] = d.y;
        }
    }
    __syncthreads();

    int pb = 0;
#pragma unroll 1
    for (int j = 1; j < LCH; ++j) {
        const int t = c * LCH + j;

        // prefetch this step's drive BEFORE the gemm (DRAM latency overlap)
        const float* dr = g_drive + ((size_t)t * BB + b0 + roff) * SS + s0;
        float2 dv[8];
#pragma unroll
        for (int r = 0; r < 8; ++r) dv[r] = *(const float2*)(dr + (size_t)r * SS);

        unsigned long long acc0[4], acc1[4];
#pragma unroll
        for (int q = 0; q < 4; ++q) { acc0[q] = 0ull; acc1[q] = 0ull; }

        gemm_q<SS / 8>(sx[pb], roff, g_At + s0, acc0, acc1);

#pragma unroll
        for (int q = 0; q < 4; ++q) {
            add2(acc0[q], pack2(dv[2 * q].x, dv[2 * q + 1].x));
            add2(acc1[q], pack2(dv[2 * q].y, dv[2 * q + 1].y));
        }

        ulonglong2* q0 = (ulonglong2*)(&sx[1 - pb][s0][roff]);
        ulonglong2* q1 = (ulonglong2*)(&sx[1 - pb][s0 + 1][roff]);
        q0[0] = make_ulonglong2(acc0[0], acc0[1]);
        q0[1] = make_ulonglong2(acc0[2], acc0[3]);
        q1[0] = make_ulonglong2(acc1[0], acc1[1]);
        q1[1] = make_ulonglong2(acc1[2], acc1[3]);
        __syncthreads();
        pb = 1 - pb;
    }
#pragma unroll
    for (int r = 0; r < 8; ++r)
        *(float2*)(&g_localEnd[((size_t)c * BB + b0 + roff + r) * SS + s0]) =
            make_float2(sx[pb][s0][roff + r], sx[pb][s0 + 1][roff + r]);
}

// ---------------- pass2: boundary recurrence ----------------
__global__ void __launch_bounds__(128) k_pass2(const float* __restrict__ x0) {
    const int b0 = blockIdx.x * 2;   // 32 CTAs
    const int s0 = 2 * threadIdx.x;
    __shared__ __align__(8) float sxp[SS][2];   // [k][row]

    float2 vA = *(const float2*)(&x0[(size_t)b0 * SS + s0]);
    float2 vB = *(const float2*)(&x0[(size_t)(b0 + 1) * SS + s0]);
    sxp[s0][0] = vA.x;     sxp[s0][1] = vB.x;
    sxp[s0 + 1][0] = vA.y; sxp[s0 + 1][1] = vB.y;
    *(float2*)(&g_xstart[((size_t)b0) * SS + s0])       = vA;
    *(float2*)(&g_xstart[((size_t)(b0 + 1)) * SS + s0]) = vB;
    __syncthreads();

#pragma unroll 1
    for (int c = 1; c < CCH; ++c) {
        float2 eA = *(const float2*)(&g_localEnd[((size_t)(c - 1) * BB + b0) * SS + s0]);
        float2 eB = *(const float2*)(&g_localEnd[((size_t)(c - 1) * BB + b0 + 1) * SS + s0]);
        unsigned long long acc0[4], acc1[4];
#pragma unroll
        for (int u = 0; u < 4; ++u) { acc0[u] = 0ull; acc1[u] = 0ull; }
        const float* wp = g_PA + s0;   // (A^T)^32
#pragma unroll 2
        for (int k = 0; k < SS; k += 4) {
#pragma unroll
            for (int u = 0; u < 4; ++u) {
                float2 w = *(const float2*)(wp + (size_t)(k + u) * SS);
                unsigned long long xp = *(const unsigned long long*)(&sxp[k + u][0]);
                fma2(acc0[u], xp, pack2(w.x, w.x));
                fma2(acc1[u], xp, pack2(w.y, w.y));
            }
        }
        add2(acc0[0], acc0[1]); add2(acc0[2], acc0[3]); add2(acc0[0], acc0[2]);
        add2(acc1[0], acc1[1]); add2(acc1[2], acc1[3]); add2(acc1[0], acc1[2]);
        float2 f0 = unpack2(acc0[0]);
        float2 f1 = unpack2(acc1[0]);
        f0.x += eA.x; f0.y += eB.x;
        f1.x += eA.y; f1.y += eB.y;
        __syncthreads();
        sxp[s0][0] = f0.x;     sxp[s0][1] = f0.y;
        sxp[s0 + 1][0] = f1.x; sxp[s0 + 1][1] = f1.y;
        __syncthreads();
        *(float2*)(&g_xstart[((size_t)c * BB + b0) * SS + s0])     = make_float2(f0.x, f1.x);
        *(float2*)(&g_xstart[((size_t)c * BB + b0 + 1) * SS + s0]) = make_float2(f0.y, f1.y);
    }
}

// ---------------- pass3 ----------------
__global__ void __launch_bounds__(512) k_pass3(float* __restrict__ out, int dup) {
    const int c    = blockIdx.x / NBT;
    const int b0   = (blockIdx.x % NBT) * BT;
    const int tid  = threadIdx.x;
    const int h    = tid >> 7;
    const int lane = tid & 127;
    const int s0   = 2 * lane;
    const int roff = 8 * h;
    __shared__ __align__(16) float sx[2][SS][PAD];

#pragma unroll
    for (int r = 0; r < 8; ++r) {
        float2 v = *(const float2*)(&g_xstart[((size_t)c * BB + b0 + roff + r) * SS + s0]);
        sx[0][s0][roff + r]     = v.x;
        sx[0][s0 + 1][roff + r] = v.y;
    }
    __syncthreads();

    float* out2 = out + (size_t)TBS;
    int pb = 0;

#pragma unroll 1
    for (int j = 0; j < LCH; ++j) {
        const int t = c * LCH + j;

        const float* dr = g_drive + ((size_t)t * BB + b0 + roff) * SS + s0;
        float2 dv[8];
#pragma unroll
        for (int r = 0; r < 8; ++r) dv[r] = *(const float2*)(dr + (size_t)r * SS);

        unsigned long long acc0[4], acc1[4];
#pragma unroll
        for (int q = 0; q < 4; ++q) { acc0[q] = 0ull; acc1[q] = 0ull; }

        gemm_q<SS / 8>(sx[pb], roff, g_At + s0, acc0, acc1);

#pragma unroll
        for (int q = 0; q < 4; ++q) {
            add2(acc0[q], pack2(dv[2 * q].x, dv[2 * q + 1].x));
            add2(acc1[q], pack2(dv[2 * q].y, dv[2 * q + 1].y));
        }

        ulonglong2* q0 = (ulonglong2*)(&sx[1 - pb][s0][roff]);
        ulonglong2* q1 = (ulonglong2*)(&sx[1 - pb][s0 + 1][roff]);
        q0[0] = make_ulonglong2(acc0[0], acc0[1]);
        q0[1] = make_ulonglong2(acc0[2], acc0[3]);
        q1[0] = make_ulonglong2(acc1[0], acc1[1]);
        q1[1] = make_ulonglong2(acc1[2], acc1[3]);

        size_t obase = ((size_t)t * BB + b0 + roff) * SS + s0;
#pragma unroll
        for (int q = 0; q < 4; ++q) {
            float2 f0 = unpack2(acc0[q]);
            float2 f1 = unpack2(acc1[q]);
            float2 oA = make_float2(f0.x, f1.x);
            float2 oB = make_float2(f0.y, f1.y);
            size_t oa = obase + (size_t)(2 * q) * SS;
            size_t ob = obase + (size_t)(2 * q + 1) * SS;
            *(float2*)(&out[oa]) = oA;
            *(float2*)(&out[ob]) = oB;
            if (dup) {
                *(float2*)(&out2[oa]) = oA;
                *(float2*)(&out2[ob]) = oB;
            }
        }
        __syncthreads();
        pb = 1 - pb;
    }
}

// ---------------- launcher ----------------
extern "C" void kernel_launch(void* const* d_in, const int* in_sizes, int n_in,
                              void* d_out, int out_size) {
    const float* x  = (const float*)d_in[0];
    const float* U  = (const float*)d_in[1];
    const float* D  = (const float*)d_in[2];
    const float* Aw = (const float*)d_in[3];
    const float* Bw = (const float*)d_in[4];
    const float* Ew = (const float*)d_in[5];
    float* out = (float*)d_out;
    int dup = (out_size >= 2 * TBS) ? 1 : 0;

    k_prep<<<(SS * SS + WK * SS + 255) / 256, 256>>>(Aw, Bw, Ew);   // 0
    k_drive<<<(TT * BB) / 32, 512>>>(U, D);                          // 1
    k_powers<<<SS / 2, 256>>>();                                     // 2
    k_pass1<<<(CCH - 1) * NBT, 512>>>();                             // 3
    k_pass2<<<BB / 2, 128>>>(x);                                     // 4
    k_pass3<<<CCH * NBT, 512>>>(out, dup);                           // 5
}

// round 14
// speedup vs baseline: 1.1218x; 1.1140x over previous
#include <cuda_runtime.h>
#include <cuda_fp16.h>
#include <cstdint>
#include <cstddef>

#define TT 2048
#define BB 64
#define SS 256
#define INK 64
#define DK 32
#define WK 96
#define CCH 64
#define LCH 32
#define TBS (TT*BB*SS)
#define PAD 36

// scan smem: 528B row stride (256 fp16 + 8 pad)
#define ROWB 528
#define SM_X0 0
#define SM_X1 (64 * ROWB)
#define SM_A0 (2 * 64 * ROWB)
#define SM_A1 (SM_A0 + 128 * ROWB)
#define SM_SCAN_TOT (SM_A1 + 128 * ROWB)   // 202752

__device__ float g_At[SS*SS];
__device__ float g_Wt[WK*SS];
__device__ float g_PA[SS*SS];
__device__ float g_PB[SS*SS];
__device__ float g_drive[TBS];
__device__ float g_localEnd[(CCH-1)*BB*SS];
__device__ float g_xstart[CCH*BB*SS];
__device__ unsigned g_sync;
// gmem staging for cross-CTA X exchange (u32 = 2 packed fp16)
__device__ uint32_t g_xb0[CCH * BB * (SS/2)];
__device__ uint32_t g_xb1[CCH * BB * (SS/2)];

// ---- f32x2 helpers ----
__device__ __forceinline__ void fma2(unsigned long long& a, unsigned long long x, unsigned long long w) {
    asm("fma.rn.f32x2 %0, %1, %2, %0;" : "+l"(a) : "l"(x), "l"(w));
}
__device__ __forceinline__ void add2(unsigned long long& a, unsigned long long x) {
    asm("add.rn.f32x2 %0, %1, %0;" : "+l"(a) : "l"(x));
}
__device__ __forceinline__ unsigned long long pack2(float lo, float hi) {
    unsigned long long r; asm("mov.b64 %0, {%1, %2};" : "=l"(r) : "f"(lo), "f"(hi)); return r;
}
__device__ __forceinline__ float2 unpack2(unsigned long long v) {
    float2 f; asm("mov.b64 {%0, %1}, %2;" : "=f"(f.x), "=f"(f.y) : "l"(v)); return f;
}

// ---- cluster / mma helpers ----
__device__ __forceinline__ uint32_t smem_u32(const void* p) {
    uint32_t a; asm("{ .reg .u64 t; cvta.to.shared.u64 t, %1; cvt.u32.u64 %0, t; }" : "=r"(a) : "l"(p)); return a;
}
__device__ __forceinline__ uint32_t ctarank() {
    uint32_t r; asm("mov.u32 %0, %%cluster_ctarank;" : "=r"(r)); return r;
}
#define CLUSTER_SYNC() do { \
    asm volatile("barrier.cluster.arrive.aligned;" ::: "memory"); \
    asm volatile("barrier.cluster.wait.aligned;"   ::: "memory"); \
} while (0)

__device__ __forceinline__ uint32_t lds_u32(uint32_t addr) {
    uint32_t v; asm volatile("ld.shared.b32 %0, [%1];" : "=r"(v) : "r"(addr)); return v;
}
__device__ __forceinline__ void mma16816(float c[4], const uint32_t a[4], const uint32_t b[2]) {
    asm volatile(
        "mma.sync.aligned.m16n8k16.row.col.f32.f16.f16.f32 "
        "{%0,%1,%2,%3}, {%4,%5,%6,%7}, {%8,%9}, {%0,%1,%2,%3};"
        : "+f"(c[0]), "+f"(c[1]), "+f"(c[2]), "+f"(c[3])
        : "r"(a[0]), "r"(a[1]), "r"(a[2]), "r"(a[3]), "r"(b[0]), "r"(b[1]));
}
__device__ __forceinline__ uint32_t h2pack(float lo, float hi) {
    __half2 h = __floats2half2_rn(lo, hi);
    return *(uint32_t*)&h;
}

// ---- prep ----
__global__ void __launch_bounds__(256) k_prep(const float* __restrict__ A,
                                              const float* __restrict__ Bw,
                                              const float* __restrict__ Ew) {
    int idx = blockIdx.x * blockDim.x + threadIdx.x;
    if (idx == 0) g_sync = 0u;
    if (idx < SS * SS) {
        int k = idx / SS, s = idx % SS;
        g_At[idx] = A[s * SS + k];
    } else {
        int j = idx - SS * SS;
        if (j < WK * SS) {
            int i = j / SS, s = j % SS;
            g_Wt[j] = (i < INK) ? Bw[s * INK + i] : Ew[s * DK + (i - INK)];
        }
    }
}

// ---- fp32 drive (proven) ----
template <int KTILES>
__device__ __forceinline__ void gemm_q(const float (*sx)[PAD], int roff, const float* wbase,
                                       unsigned long long a0[4], unsigned long long a1[4]) {
    float2 wv[8];
#pragma unroll
    for (int i = 0; i < 8; ++i) wv[i] = *(const float2*)(wbase + (size_t)i * SS);
#pragma unroll 1
    for (int kt = 0; kt < KTILES; ++kt) {
        float2 wn[8];
        if (kt < KTILES - 1) {
#pragma unroll
            for (int i = 0; i < 8; ++i) wn[i] = *(const float2*)(wbase + (size_t)((kt + 1) * 8 + i) * SS);
        }
#pragma unroll
        for (int i = 0; i < 8; ++i) {
            const int k = kt * 8 + i;
            unsigned long long w0 = pack2(wv[i].x, wv[i].x), w1 = pack2(wv[i].y, wv[i].y);
            const ulonglong2* xv = (const ulonglong2*)(&sx[k][roff]);
            ulonglong2 v0 = xv[0], v1 = xv[1];
            fma2(a0[0], v0.x, w0); fma2(a0[1], v0.y, w0); fma2(a0[2], v1.x, w0); fma2(a0[3], v1.y, w0);
            fma2(a1[0], v0.x, w1); fma2(a1[1], v0.y, w1); fma2(a1[2], v1.x, w1); fma2(a1[3], v1.y, w1);
        }
#pragma unroll
        for (int i = 0; i < 8; ++i) wv[i] = wn[i];
    }
}

__global__ void __launch_bounds__(512) k_drive(const float* __restrict__ U, const float* __restrict__ D) {
    __shared__ __align__(16) float sRow[WK][PAD];
    const int R0 = blockIdx.x * 32, tid = threadIdx.x;
    const int h = tid >> 7, lane = tid & 127, s0 = 2 * lane, roff = 8 * h;
    for (int e = tid; e < 32 * WK; e += 512) {
        int r = e / WK, i = e % WK;
        size_t R = (size_t)(R0 + r);
        sRow[i][r] = (i < INK) ? U[R * INK + i] : D[R * DK + (i - INK)];
    }
    __syncthreads();
    unsigned long long a0[4], a1[4];
#pragma unroll
    for (int q = 0; q < 4; ++q) { a0[q] = 0ull; a1[q] = 0ull; }
    gemm_q<WK / 8>(sRow, roff, g_Wt + s0, a0, a1);
#pragma unroll
    for (int q = 0; q < 4; ++q) {
        float2 f0 = unpack2(a0[q]), f1 = unpack2(a1[q]);
        *(float2*)(&g_drive[(size_t)(R0 + roff + 2 * q) * SS + s0])     = make_float2(f0.x, f1.x);
        *(float2*)(&g_drive[(size_t)(R0 + roff + 2 * q + 1) * SS + s0]) = make_float2(f0.y, f1.y);
    }
}

// ---- powers: (A^T)^32 ----
__global__ void __launch_bounds__(256) k_powers() {
    __shared__ float sRow[2][SS];
    const int tid = threadIdx.x, k0 = blockIdx.x * 2;
    const float* src = g_At;
    float* dst = g_PA;
#pragma unroll 1
    for (int step = 0; step < 5; ++step) {
        sRow[0][tid] = src[(size_t)k0 * SS + tid];
        sRow[1][tid] = src[(size_t)(k0 + 1) * SS + tid];
        __syncthreads();
        float a0 = 0.f, a1 = 0.f;
#pragma unroll 4
        for (int j = 0; j < SS; ++j) {
            float b = src[(size_t)j * SS + tid];
            a0 = fmaf(sRow[0][j], b, a0);
            a1 = fmaf(sRow[1][j], b, a1);
        }
        dst[(size_t)k0 * SS + tid] = a0;
        dst[(size_t)(k0 + 1) * SS + tid] = a1;
        __syncthreads();
        if (tid == 0) {
            __threadfence();
            atomicAdd(&g_sync, 1u);
            unsigned tgt = 128u * (unsigned)(step + 1);
            while (*((volatile unsigned*)&g_sync) < tgt) { __nanosleep(64); }
        }
        __syncthreads();
        src = dst;
        dst = (dst == g_PA) ? g_PB : g_PA;
    }
}

// ---- warp-MMA scan with per-chunk power-of-2 scaling ----
// 2-CTA cluster per chunk; CTA rank owns output cols [rank*128, +128).
template <int MODE>
__global__ void __launch_bounds__(256) __cluster_dims__(2, 1, 1)
k_scan_mma(const float* __restrict__ Aw, float* __restrict__ out, int dup) {
    extern __shared__ __align__(16) char sm[];
    __shared__ float smax[9];
    const uint32_t sb = smem_u32(sm);
    const int tid = threadIdx.x;
    const int w = tid >> 5, lane = tid & 31;
    const uint32_t rank = ctarank();
    const int chunk = blockIdx.x >> 1;

    // A rows [rank*128, +128) x K=256, fp16 split-2
    for (int e = tid; e < 128 * 256; e += 256) {
        int r = e >> 8, k = e & 255;
        float v = Aw[(size_t)((int)rank * 128 + r) * SS + k];
        __half q0 = __float2half_rn(v);
        __half q1 = __float2half_rn(v - __half2float(q0));
        *(__half*)(sm + SM_A0 + r * ROWB + k * 2) = q0;
        *(__half*)(sm + SM_A1 + r * ROWB + k * 2) = q1;
    }

    // --- compute per-chunk max|x_start| (both CTAs: same data, same result) ---
    const float* xsrc = (MODE == 1) ? (g_drive + (size_t)(chunk * LCH) * BB * SS)
                                    : (g_xstart + (size_t)chunk * BB * SS);
    {
        float mymax = 0.f;
        for (int e = tid; e < 64 * 256; e += 256) mymax = fmaxf(mymax, fabsf(xsrc[e]));
#pragma unroll
        for (int o = 16; o; o >>= 1) mymax = fmaxf(mymax, __shfl_xor_sync(0xFFFFFFFFu, mymax, o));
        if (lane == 0) smax[w] = mymax;
        __syncthreads();
        if (tid == 0) {
            float m = smax[0];
#pragma unroll
            for (int i = 1; i < 8; ++i) m = fmaxf(m, smax[i]);
            smax[8] = m;
        }
        __syncthreads();
    }
    const float maxv = smax[8];
    const int ex = (maxv > 1e-30f) ? ilogbf(maxv) : 0;
    const float sc  = ldexpf(1.0f, -ex);   // exact power of 2
    const float inv = ldexpf(1.0f,  ex);

    // X init (scaled) fp16 split-2
    for (int e = tid; e < 64 * 256; e += 256) {
        int b = e >> 8, k = e & 255;
        float v = xsrc[(size_t)b * SS + k] * sc;
        __half q0 = __float2half_rn(v);
        __half q1 = __float2half_rn(v - __half2float(q0));
        *(__half*)(sm + SM_X0 + b * ROWB + k * 2) = q0;
        *(__half*)(sm + SM_X1 + b * ROWB + k * 2) = q1;
    }
    __syncthreads();

    // fragment index pieces (PTX m16n8k16 tables, direct addressing)
    const int qrow = lane >> 2;
    const uint32_t cb = (uint32_t)(lane & 3) * 4;
    const int n0 = w * 16;
    const int colg = (int)rank * 128 + n0 + 2 * (lane & 3);
    const int peerR = (int)(rank ^ 1u);

    const int j0 = (MODE == 1) ? 1 : 0;

#pragma unroll 1
    for (int j = j0; j < LCH; ++j) {
        const int t = chunk * LCH + j;

        float acc[2][4][4];
#pragma unroll
        for (int nt = 0; nt < 2; ++nt)
#pragma unroll
            for (int m = 0; m < 4; ++m)
#pragma unroll
                for (int q = 0; q < 4; ++q) acc[nt][m][q] = 0.f;

        // prefetch drive (raw fp32; scaled at add time)
        float2 dv[2][4][2];
        const float* drp = g_drive + (size_t)t * BB * SS;
#pragma unroll
        for (int nt = 0; nt < 2; ++nt)
#pragma unroll
            for (int m = 0; m < 4; ++m)
#pragma unroll
                for (int i = 0; i < 2; ++i)
                    dv[nt][m][i] = *(const float2*)(drp + (size_t)(m * 16 + qrow + i * 8) * SS + colg + nt * 8);

#pragma unroll 1
        for (int kt = 0; kt < 16; ++kt) {
            const uint32_t kb = (uint32_t)kt * 32;
            uint32_t ax0[4][4], ax1[4][4];
#pragma unroll
            for (int m = 0; m < 4; ++m) {
                uint32_t b0a = sb + SM_X0 + (uint32_t)(m * 16 + qrow) * ROWB + cb + kb;
                uint32_t b1a = sb + SM_X1 + (uint32_t)(m * 16 + qrow) * ROWB + cb + kb;
                ax0[m][0] = lds_u32(b0a);
                ax0[m][1] = lds_u32(b0a + 8u * ROWB);
                ax0[m][2] = lds_u32(b0a + 16u);
                ax0[m][3] = lds_u32(b0a + 8u * ROWB + 16u);
                ax1[m][0] = lds_u32(b1a);
                ax1[m][1] = lds_u32(b1a + 8u * ROWB);
                ax1[m][2] = lds_u32(b1a + 16u);
                ax1[m][3] = lds_u32(b1a + 8u * ROWB + 16u);
            }
            uint32_t bb0[2][2], bb1[2][2];
#pragma unroll
            for (int nt = 0; nt < 2; ++nt) {
                uint32_t ba0 = sb + SM_A0 + (uint32_t)(n0 + nt * 8 + qrow) * ROWB + cb + kb;
                uint32_t ba1 = sb + SM_A1 + (uint32_t)(n0 + nt * 8 + qrow) * ROWB + cb + kb;
                bb0[nt][0] = lds_u32(ba0);
                bb0[nt][1] = lds_u32(ba0 + 16u);
                bb1[nt][0] = lds_u32(ba1);
                bb1[nt][1] = lds_u32(ba1 + 16u);
            }
#pragma unroll
            for (int nt = 0; nt < 2; ++nt)
#pragma unroll
                for (int m = 0; m < 4; ++m) {
                    mma16816(acc[nt][m], ax0[m], bb0[nt]);   // X0*A0
                    mma16816(acc[nt][m], ax1[m], bb0[nt]);   // X1*A0
                    mma16816(acc[nt][m], ax0[m], bb1[nt]);   // X0*A1
                }
        }

        __syncthreads();   // all LDS reads of X done before overwriting own half

        // finalize own cols: scaled new state + outputs (x inv)
#pragma unroll
        for (int nt = 0; nt < 2; ++nt)
#pragma unroll
            for (int m = 0; m < 4; ++m)
#pragma unroll
                for (int i = 0; i < 2; ++i) {
                    float v0 = acc[nt][m][2 * i]     + dv[nt][m][i].x * sc;
                    float v1 = acc[nt][m][2 * i + 1] + dv[nt][m][i].y * sc;
                    const int row  = m * 16 + qrow + i * 8;
                    const int kcol = colg + nt * 8;

                    if (MODE == 3) {
                        float* o1 = out + (size_t)t * BB * SS + (size_t)row * SS + kcol;
                        *(float2*)o1 = make_float2(v0 * inv, v1 * inv);
                        if (dup) *(float2*)(o1 + (size_t)TBS) = make_float2(v0 * inv, v1 * inv);
                    }
                    if (MODE == 1 && j == LCH - 1) {
                        float* le = g_localEnd + (size_t)chunk * BB * SS + (size_t)row * SS + kcol;
                        *(float2*)le = make_float2(v0 * inv, v1 * inv);
                    }

                    __half h0 = __float2half_rn(v0);
                    __half h1 = __float2half_rn(v1);
                    uint32_t p0 = h2pack(v0, v1);
                    uint32_t p1 = h2pack(v0 - __half2float(h0), v1 - __half2float(h1));
                    // own half -> local smem directly
                    const uint32_t off = (uint32_t)row * ROWB + (uint32_t)kcol * 2;
                    *(uint32_t*)(sm + SM_X0 + off) = p0;
                    *(uint32_t*)(sm + SM_X1 + off) = p1;
                    // and to gmem staging for the peer
                    const size_t gi = ((size_t)chunk * BB + row) * (SS / 2) + (kcol >> 1);
                    g_xb0[gi] = p0;
                    g_xb1[gi] = p1;
                }

        __threadfence();
        CLUSTER_SYNC();   // peer's staging writes visible

        // reload ONLY the peer's col half from staging
        for (int e = tid; e < 64 * 64; e += 256) {
            int row = e >> 6, c2 = peerR * 64 + (e & 63);
            const size_t gi = ((size_t)chunk * BB + row) * (SS / 2) + c2;
            *(uint32_t*)(sm + SM_X0 + row * ROWB + c2 * 4) = g_xb0[gi];
            *(uint32_t*)(sm + SM_X1 + row * ROWB + c2 * 4) = g_xb1[gi];
        }
        CLUSTER_SYNC();   // X rebuilt; staging reusable next step
    }
}

// ---- pass2: boundary recurrence (fp32, proven) ----
__global__ void __launch_bounds__(128) k_pass2(const float* __restrict__ x0) {
    const int b0 = blockIdx.x * 2;
    const int s0 = 2 * threadIdx.x;
    __shared__ __align__(8) float sxp[SS][2];

    float2 vA = *(const float2*)(&x0[(size_t)b0 * SS + s0]);
    float2 vB = *(const float2*)(&x0[(size_t)(b0 + 1) * SS + s0]);
    sxp[s0][0] = vA.x;     sxp[s0][1] = vB.x;
    sxp[s0 + 1][0] = vA.y; sxp[s0 + 1][1] = vB.y;
    *(float2*)(&g_xstart[((size_t)b0) * SS + s0])       = vA;
    *(float2*)(&g_xstart[((size_t)(b0 + 1)) * SS + s0]) = vB;
    __syncthreads();

#pragma unroll 1
    for (int c = 1; c < CCH; ++c) {
        float2 eA = *(const float2*)(&g_localEnd[((size_t)(c - 1) * BB + b0) * SS + s0]);
        float2 eB = *(const float2*)(&g_localEnd[((size_t)(c - 1) * BB + b0 + 1) * SS + s0]);
        unsigned long long a0[4], a1[4];
#pragma unroll
        for (int u = 0; u < 4; ++u) { a0[u] = 0ull; a1[u] = 0ull; }
        const float* wp = g_PA + s0;
#pragma unroll 2
        for (int k = 0; k < SS; k += 4) {
#pragma unroll
            for (int u = 0; u < 4; ++u) {
                float2 wv = *(const float2*)(wp + (size_t)(k + u) * SS);
                unsigned long long xp = *(const unsigned long long*)(&sxp[k + u][0]);
                fma2(a0[u], xp, pack2(wv.x, wv.x));
                fma2(a1[u], xp, pack2(wv.y, wv.y));
            }
        }
        add2(a0[0], a0[1]); add2(a0[2], a0[3]); add2(a0[0], a0[2]);
        add2(a1[0], a1[1]); add2(a1[2], a1[3]); add2(a1[0], a1[2]);
        float2 f0 = unpack2(a0[0]), f1 = unpack2(a1[0]);
        f0.x += eA.x; f0.y += eB.x;
        f1.x += eA.y; f1.y += eB.y;
        __syncthreads();
        sxp[s0][0] = f0.x;     sxp[s0][1] = f0.y;
        sxp[s0 + 1][0] = f1.x; sxp[s0 + 1][1] = f1.y;
        __syncthreads();
        *(float2*)(&g_xstart[((size_t)c * BB + b0) * SS + s0])     = make_float2(f0.x, f1.x);
        *(float2*)(&g_xstart[((size_t)c * BB + b0 + 1) * SS + s0]) = make_float2(f0.y, f1.y);
    }
}

// ---- launcher ----
extern "C" void kernel_launch(void* const* d_in, const int* in_sizes, int n_in,
                              void* d_out, int out_size) {
    const float* x  = (const float*)d_in[0];
    const float* U  = (const float*)d_in[1];
    const float* D  = (const float*)d_in[2];
    const float* Aw = (const float*)d_in[3];
    const float* Bw = (const float*)d_in[4];
    const float* Ew = (const float*)d_in[5];
    float* out = (float*)d_out;
    int dup = (out_size >= 2 * TBS) ? 1 : 0;

    cudaFuncSetAttribute(k_scan_mma<1>, cudaFuncAttributeMaxDynamicSharedMemorySize, SM_SCAN_TOT);
    cudaFuncSetAttribute(k_scan_mma<3>, cudaFuncAttributeMaxDynamicSharedMemorySize, SM_SCAN_TOT);

    k_prep<<<(SS * SS + WK * SS + 255) / 256, 256>>>(Aw, Bw, Ew);     // 0
    k_drive<<<(TT * BB) / 32, 512>>>(U, D);                            // 1
    k_powers<<<SS / 2, 256>>>();                                       // 2
    k_scan_mma<1><<<(CCH - 1) * 2, 256, SM_SCAN_TOT>>>(Aw, out, 0);    // 3 (pass1)
    k_pass2<<<BB / 2, 128>>>(x);                                       // 4
    k_scan_mma<3><<<CCH * 2, 256, SM_SCAN_TOT>>>(Aw, out, dup);        // 5 (pass3)
}

// round 15
// speedup vs baseline: 1.1982x; 1.0681x over previous
#include <cuda_runtime.h>
#include <cuda_fp16.h>
#include <cstdint>
#include <cstddef>

#define TT 2048
#define BB 64
#define SS 256
#define INK 64
#define DK 32
#define WK 96
#define CCH 64
#define LCH 32
#define TBS (TT*BB*SS)
#define PAD 36

// scan smem: 528B row stride (256 fp16 + 8 pad)
#define ROWB 528
#define SM_X0 0
#define SM_X1 (64 * ROWB)
#define SM_A0 (2 * 64 * ROWB)
#define SM_A1 (SM_A0 + 128 * ROWB)
#define SM_SCAN_TOT (SM_A1 + 128 * ROWB)   // 202752

__device__ float g_At[SS*SS];
__device__ float g_Wt[WK*SS];
__device__ float g_PA[SS*SS];
__device__ float g_PB[SS*SS];
__device__ float g_drive[TBS];
__device__ float g_localEnd[(CCH-1)*BB*SS];
__device__ float g_xstart[CCH*BB*SS];
__device__ unsigned g_sync;

// ---- f32x2 helpers ----
__device__ __forceinline__ void fma2(unsigned long long& a, unsigned long long x, unsigned long long w) {
    asm("fma.rn.f32x2 %0, %1, %2, %0;" : "+l"(a) : "l"(x), "l"(w));
}
__device__ __forceinline__ void add2(unsigned long long& a, unsigned long long x) {
    asm("add.rn.f32x2 %0, %1, %0;" : "+l"(a) : "l"(x));
}
__device__ __forceinline__ unsigned long long pack2(float lo, float hi) {
    unsigned long long r; asm("mov.b64 %0, {%1, %2};" : "=l"(r) : "f"(lo), "f"(hi)); return r;
}
__device__ __forceinline__ float2 unpack2(unsigned long long v) {
    float2 f; asm("mov.b64 {%0, %1}, %2;" : "=f"(f.x), "=f"(f.y) : "l"(v)); return f;
}

// ---- cluster / mma helpers ----
__device__ __forceinline__ uint32_t smem_u32(const void* p) {
    uint32_t a; asm("{ .reg .u64 t; cvta.to.shared.u64 t, %1; cvt.u32.u64 %0, t; }" : "=r"(a) : "l"(p)); return a;
}
__device__ __forceinline__ uint32_t ctarank() {
    uint32_t r; asm("mov.u32 %0, %%cluster_ctarank;" : "=r"(r)); return r;
}
__device__ __forceinline__ uint32_t mapa_peer(uint32_t addr, uint32_t peer) {
    uint32_t r; asm("mapa.shared::cluster.u32 %0, %1, %2;" : "=r"(r) : "r"(addr), "r"(peer)); return r;
}
__device__ __forceinline__ void st_cluster_b32(uint32_t addr, uint32_t v) {
    asm volatile("st.shared::cluster.b32 [%0], %1;" :: "r"(addr), "r"(v) : "memory");
}
#define CLUSTER_SYNC() do { \
    asm volatile("barrier.cluster.arrive.aligned;" ::: "memory"); \
    asm volatile("barrier.cluster.wait.aligned;"   ::: "memory"); \
} while (0)

__device__ __forceinline__ uint32_t lds_u32(uint32_t addr) {
    uint32_t v; asm volatile("ld.shared.b32 %0, [%1];" : "=r"(v) : "r"(addr)); return v;
}
__device__ __forceinline__ void mma16816(float c[4], const uint32_t a[4], const uint32_t b[2]) {
    asm volatile(
        "mma.sync.aligned.m16n8k16.row.col.f32.f16.f16.f32 "
        "{%0,%1,%2,%3}, {%4,%5,%6,%7}, {%8,%9}, {%0,%1,%2,%3};"
        : "+f"(c[0]), "+f"(c[1]), "+f"(c[2]), "+f"(c[3])
        : "r"(a[0]), "r"(a[1]), "r"(a[2]), "r"(a[3]), "r"(b[0]), "r"(b[1]));
}
__device__ __forceinline__ uint32_t h2pack(float lo, float hi) {
    __half2 h = __floats2half2_rn(lo, hi);
    return *(uint32_t*)&h;
}

// ---- prep ----
__global__ void __launch_bounds__(256) k_prep(const float* __restrict__ A,
                                              const float* __restrict__ Bw,
                                              const float* __restrict__ Ew) {
    int idx = blockIdx.x * blockDim.x + threadIdx.x;
    if (idx == 0) g_sync = 0u;
    if (idx < SS * SS) {
        int k = idx / SS, s = idx % SS;
        g_At[idx] = A[s * SS + k];
    } else {
        int j = idx - SS * SS;
        if (j < WK * SS) {
            int i = j / SS, s = j % SS;
            g_Wt[j] = (i < INK) ? Bw[s * INK + i] : Ew[s * DK + (i - INK)];
        }
    }
}

// ---- fp32 drive (proven) ----
template <int KTILES>
__device__ __forceinline__ void gemm_q(const float (*sx)[PAD], int roff, const float* wbase,
                                       unsigned long long a0[4], unsigned long long a1[4]) {
    float2 wv[8];
#pragma unroll
    for (int i = 0; i < 8; ++i) wv[i] = *(const float2*)(wbase + (size_t)i * SS);
#pragma unroll 1
    for (int kt = 0; kt < KTILES; ++kt) {
        float2 wn[8];
        if (kt < KTILES - 1) {
#pragma unroll
            for (int i = 0; i < 8; ++i) wn[i] = *(const float2*)(wbase + (size_t)((kt + 1) * 8 + i) * SS);
        }
#pragma unroll
        for (int i = 0; i < 8; ++i) {
            const int k = kt * 8 + i;
            unsigned long long w0 = pack2(wv[i].x, wv[i].x), w1 = pack2(wv[i].y, wv[i].y);
            const ulonglong2* xv = (const ulonglong2*)(&sx[k][roff]);
            ulonglong2 v0 = xv[0], v1 = xv[1];
            fma2(a0[0], v0.x, w0); fma2(a0[1], v0.y, w0); fma2(a0[2], v1.x, w0); fma2(a0[3], v1.y, w0);
            fma2(a1[0], v0.x, w1); fma2(a1[1], v0.y, w1); fma2(a1[2], v1.x, w1); fma2(a1[3], v1.y, w1);
        }
#pragma unroll
        for (int i = 0; i < 8; ++i) wv[i] = wn[i];
    }
}

__global__ void __launch_bounds__(512) k_drive(const float* __restrict__ U, const float* __restrict__ D) {
    __shared__ __align__(16) float sRow[WK][PAD];
    const int R0 = blockIdx.x * 32, tid = threadIdx.x;
    const int h = tid >> 7, lane = tid & 127, s0 = 2 * lane, roff = 8 * h;
    for (int e = tid; e < 32 * WK; e += 512) {
        int r = e / WK, i = e % WK;
        size_t R = (size_t)(R0 + r);
        sRow[i][r] = (i < INK) ? U[R * INK + i] : D[R * DK + (i - INK)];
    }
    __syncthreads();
    unsigned long long a0[4], a1[4];
#pragma unroll
    for (int q = 0; q < 4; ++q) { a0[q] = 0ull; a1[q] = 0ull; }
    gemm_q<WK / 8>(sRow, roff, g_Wt + s0, a0, a1);
#pragma unroll
    for (int q = 0; q < 4; ++q) {
        float2 f0 = unpack2(a0[q]), f1 = unpack2(a1[q]);
        *(float2*)(&g_drive[(size_t)(R0 + roff + 2 * q) * SS + s0])     = make_float2(f0.x, f1.x);
        *(float2*)(&g_drive[(size_t)(R0 + roff + 2 * q + 1) * SS + s0]) = make_float2(f0.y, f1.y);
    }
}

// ---- powers: (A^T)^32 ----
__global__ void __launch_bounds__(256) k_powers() {
    __shared__ float sRow[2][SS];
    const int tid = threadIdx.x, k0 = blockIdx.x * 2;
    const float* src = g_At;
    float* dst = g_PA;
#pragma unroll 1
    for (int step = 0; step < 5; ++step) {
        sRow[0][tid] = src[(size_t)k0 * SS + tid];
        sRow[1][tid] = src[(size_t)(k0 + 1) * SS + tid];
        __syncthreads();
        float a0 = 0.f, a1 = 0.f;
#pragma unroll 4
        for (int j = 0; j < SS; ++j) {
            float b = src[(size_t)j * SS + tid];
            a0 = fmaf(sRow[0][j], b, a0);
            a1 = fmaf(sRow[1][j], b, a1);
        }
        dst[(size_t)k0 * SS + tid] = a0;
        dst[(size_t)(k0 + 1) * SS + tid] = a1;
        __syncthreads();
        if (tid == 0) {
            __threadfence();
            atomicAdd(&g_sync, 1u);
            unsigned tgt = 128u * (unsigned)(step + 1);
            while (*((volatile unsigned*)&g_sync) < tgt) { __nanosleep(64); }
        }
        __syncthreads();
        src = dst;
        dst = (dst == g_PA) ? g_PB : g_PA;
    }
}

// ---- warp-MMA scan with per-chunk power-of-2 scaling + DSMEM exchange ----
// 2-CTA cluster per chunk; CTA rank owns output cols [rank*128, +128).
template <int MODE>
__global__ void __launch_bounds__(256) __cluster_dims__(2, 1, 1)
k_scan_mma(const float* __restrict__ Aw, float* __restrict__ out, int dup) {
    extern __shared__ __align__(16) char sm[];
    __shared__ float smax[9];
    const uint32_t sb = smem_u32(sm);
    const int tid = threadIdx.x;
    const int w = tid >> 5, lane = tid & 31;
    const uint32_t rank = ctarank();
    const int chunk = blockIdx.x >> 1;

    // A rows [rank*128, +128) x K=256, fp16 split-2
    for (int e = tid; e < 128 * 256; e += 256) {
        int r = e >> 8, k = e & 255;
        float v = Aw[(size_t)((int)rank * 128 + r) * SS + k];
        __half q0 = __float2half_rn(v);
        __half q1 = __float2half_rn(v - __half2float(q0));
        *(__half*)(sm + SM_A0 + r * ROWB + k * 2) = q0;
        *(__half*)(sm + SM_A1 + r * ROWB + k * 2) = q1;
    }

    // per-chunk max|x_start| (both CTAs compute identically)
    const float* xsrc = (MODE == 1) ? (g_drive + (size_t)(chunk * LCH) * BB * SS)
                                    : (g_xstart + (size_t)chunk * BB * SS);
    {
        float mymax = 0.f;
        for (int e = tid; e < 64 * 256; e += 256) mymax = fmaxf(mymax, fabsf(xsrc[e]));
#pragma unroll
        for (int o = 16; o; o >>= 1) mymax = fmaxf(mymax, __shfl_xor_sync(0xFFFFFFFFu, mymax, o));
        if (lane == 0) smax[w] = mymax;
        __syncthreads();
        if (tid == 0) {
            float m = smax[0];
#pragma unroll
            for (int i = 1; i < 8; ++i) m = fmaxf(m, smax[i]);
            smax[8] = m;
        }
        __syncthreads();
    }
    const float maxv = smax[8];
    const int ex = (maxv > 1e-30f) ? ilogbf(maxv) : 0;
    const float sc  = ldexpf(1.0f, -ex);   // exact power of 2
    const float inv = ldexpf(1.0f,  ex);

    // X init (scaled) fp16 split-2
    for (int e = tid; e < 64 * 256; e += 256) {
        int b = e >> 8, k = e & 255;
        float v = xsrc[(size_t)b * SS + k] * sc;
        __half q0 = __float2half_rn(v);
        __half q1 = __float2half_rn(v - __half2float(q0));
        *(__half*)(sm + SM_X0 + b * ROWB + k * 2) = q0;
        *(__half*)(sm + SM_X1 + b * ROWB + k * 2) = q1;
    }
    __syncthreads();
    CLUSTER_SYNC();   // both CTAs' X + A tiles ready

    const uint32_t peerX = mapa_peer(sb, rank ^ 1u);   // peer smem base

    // fragment index pieces (PTX m16n8k16 tables, direct addressing)
    const int qrow = lane >> 2;
    const uint32_t cb = (uint32_t)(lane & 3) * 4;
    const int n0 = w * 16;
    const int colg = (int)rank * 128 + n0 + 2 * (lane & 3);

    const int j0 = (MODE == 1) ? 1 : 0;

#pragma unroll 1
    for (int j = j0; j < LCH; ++j) {
        const int t = chunk * LCH + j;

        float acc[2][4][4];
#pragma unroll
        for (int nt = 0; nt < 2; ++nt)
#pragma unroll
            for (int m = 0; m < 4; ++m)
#pragma unroll
                for (int q = 0; q < 4; ++q) acc[nt][m][q] = 0.f;

        // prefetch drive (raw fp32; scaled at add time)
        float2 dv[2][4][2];
        const float* drp = g_drive + (size_t)t * BB * SS;
#pragma unroll
        for (int nt = 0; nt < 2; ++nt)
#pragma unroll
            for (int m = 0; m < 4; ++m)
#pragma unroll
                for (int i = 0; i < 2; ++i)
                    dv[nt][m][i] = *(const float2*)(drp + (size_t)(m * 16 + qrow + i * 8) * SS + colg + nt * 8);

#pragma unroll 2
        for (int kt = 0; kt < 16; ++kt) {
            const uint32_t kb = (uint32_t)kt * 32;
            uint32_t ax0[4][4], ax1[4][4];
#pragma unroll
            for (int m = 0; m < 4; ++m) {
                uint32_t b0a = sb + SM_X0 + (uint32_t)(m * 16 + qrow) * ROWB + cb + kb;
                uint32_t b1a = sb + SM_X1 + (uint32_t)(m * 16 + qrow) * ROWB + cb + kb;
                ax0[m][0] = lds_u32(b0a);
                ax0[m][1] = lds_u32(b0a + 8u * ROWB);
                ax0[m][2] = lds_u32(b0a + 16u);
                ax0[m][3] = lds_u32(b0a + 8u * ROWB + 16u);
                ax1[m][0] = lds_u32(b1a);
                ax1[m][1] = lds_u32(b1a + 8u * ROWB);
                ax1[m][2] = lds_u32(b1a + 16u);
                ax1[m][3] = lds_u32(b1a + 8u * ROWB + 16u);
            }
            uint32_t bb0[2][2], bb1[2][2];
#pragma unroll
            for (int nt = 0; nt < 2; ++nt) {
                uint32_t ba0 = sb + SM_A0 + (uint32_t)(n0 + nt * 8 + qrow) * ROWB + cb + kb;
                uint32_t ba1 = sb + SM_A1 + (uint32_t)(n0 + nt * 8 + qrow) * ROWB + cb + kb;
                bb0[nt][0] = lds_u32(ba0);
                bb0[nt][1] = lds_u32(ba0 + 16u);
                bb1[nt][0] = lds_u32(ba1);
                bb1[nt][1] = lds_u32(ba1 + 16u);
            }
#pragma unroll
            for (int nt = 0; nt < 2; ++nt)
#pragma unroll
                for (int m = 0; m < 4; ++m) {
                    mma16816(acc[nt][m], ax0[m], bb0[nt]);   // X0*A0
                    mma16816(acc[nt][m], ax1[m], bb0[nt]);   // X1*A0
                    mma16816(acc[nt][m], ax0[m], bb1[nt]);   // X0*A1
                }
        }

        CLUSTER_SYNC();   // BOTH CTAs finished reading X before anyone overwrites it

        // finalize own cols: write local + peer smem (DSMEM), outputs to gmem
#pragma unroll
        for (int nt = 0; nt < 2; ++nt)
#pragma unroll
            for (int m = 0; m < 4; ++m)
#pragma unroll
                for (int i = 0; i < 2; ++i) {
                    float v0 = acc[nt][m][2 * i]     + dv[nt][m][i].x * sc;
                    float v1 = acc[nt][m][2 * i + 1] + dv[nt][m][i].y * sc;
                    const int row  = m * 16 + qrow + i * 8;
                    const int kcol = colg + nt * 8;

                    if (MODE == 3) {
                        float* o1 = out + (size_t)t * BB * SS + (size_t)row * SS + kcol;
                        *(float2*)o1 = make_float2(v0 * inv, v1 * inv);
                        if (dup) *(float2*)(o1 + (size_t)TBS) = make_float2(v0 * inv, v1 * inv);
                    }
                    if (MODE == 1 && j == LCH - 1) {
                        float* le = g_localEnd + (size_t)chunk * BB * SS + (size_t)row * SS + kcol;
                        *(float2*)le = make_float2(v0 * inv, v1 * inv);
                    }

                    __half h0 = __float2half_rn(v0);
                    __half h1 = __float2half_rn(v1);
                    uint32_t p0 = h2pack(v0, v1);
                    uint32_t p1 = h2pack(v0 - __half2float(h0), v1 - __half2float(h1));
                    const uint32_t off = (uint32_t)row * ROWB + (uint32_t)kcol * 2;
                    *(uint32_t*)(sm + SM_X0 + off) = p0;
                    *(uint32_t*)(sm + SM_X1 + off) = p1;
                    st_cluster_b32(peerX + SM_X0 + off, p0);
                    st_cluster_b32(peerX + SM_X1 + off, p1);
                }

        CLUSTER_SYNC();   // all local+peer X writes visible before next step's reads
    }
}

// ---- pass2: boundary recurrence (fp32, proven) ----
__global__ void __launch_bounds__(128) k_pass2(const float* __restrict__ x0) {
    const int b0 = blockIdx.x * 2;
    const int s0 = 2 * threadIdx.x;
    __shared__ __align__(8) float sxp[SS][2];

    float2 vA = *(const float2*)(&x0[(size_t)b0 * SS + s0]);
    float2 vB = *(const float2*)(&x0[(size_t)(b0 + 1) * SS + s0]);
    sxp[s0][0] = vA.x;     sxp[s0][1] = vB.x;
    sxp[s0 + 1][0] = vA.y; sxp[s0 + 1][1] = vB.y;
    *(float2*)(&g_xstart[((size_t)b0) * SS + s0])       = vA;
    *(float2*)(&g_xstart[((size_t)(b0 + 1)) * SS + s0]) = vB;
    __syncthreads();

#pragma unroll 1
    for (int c = 1; c < CCH; ++c) {
        float2 eA = *(const float2*)(&g_localEnd[((size_t)(c - 1) * BB + b0) * SS + s0]);
        float2 eB = *(const float2*)(&g_localEnd[((size_t)(c - 1) * BB + b0 + 1) * SS + s0]);
        unsigned long long a0[4], a1[4];
#pragma unroll
        for (int u = 0; u < 4; ++u) { a0[u] = 0ull; a1[u] = 0ull; }
        const float* wp = g_PA + s0;
#pragma unroll 2
        for (int k = 0; k < SS; k += 4) {
#pragma unroll
            for (int u = 0; u < 4; ++u) {
                float2 wv = *(const float2*)(wp + (size_t)(k + u) * SS);
                unsigned long long xp = *(const unsigned long long*)(&sxp[k + u][0]);
                fma2(a0[u], xp, pack2(wv.x, wv.x));
                fma2(a1[u], xp, pack2(wv.y, wv.y));
            }
        }
        add2(a0[0], a0[1]); add2(a0[2], a0[3]); add2(a0[0], a0[2]);
        add2(a1[0], a1[1]); add2(a1[2], a1[3]); add2(a1[0], a1[2]);
        float2 f0 = unpack2(a0[0]), f1 = unpack2(a1[0]);
        f0.x += eA.x; f0.y += eB.x;
        f1.x += eA.y; f1.y += eB.y;
        __syncthreads();
        sxp[s0][0] = f0.x;     sxp[s0][1] = f0.y;
        sxp[s0 + 1][0] = f1.x; sxp[s0 + 1][1] = f1.y;
        __syncthreads();
        *(float2*)(&g_xstart[((size_t)c * BB + b0) * SS + s0])     = make_float2(f0.x, f1.x);
        *(float2*)(&g_xstart[((size_t)c * BB + b0 + 1) * SS + s0]) = make_float2(f0.y, f1.y);
    }
}

// ---- launcher ----
extern "C" void kernel_launch(void* const* d_in, const int* in_sizes, int n_in,
                              void* d_out, int out_size) {
    const float* x  = (const float*)d_in[0];
    const float* U  = (const float*)d_in[1];
    const float* D  = (const float*)d_in[2];
    const float* Aw = (const float*)d_in[3];
    const float* Bw = (const float*)d_in[4];
    const float* Ew = (const float*)d_in[5];
    float* out = (float*)d_out;
    int dup = (out_size >= 2 * TBS) ? 1 : 0;

    cudaFuncSetAttribute(k_scan_mma<1>, cudaFuncAttributeMaxDynamicSharedMemorySize, SM_SCAN_TOT);
    cudaFuncSetAttribute(k_scan_mma<3>, cudaFuncAttributeMaxDynamicSharedMemorySize, SM_SCAN_TOT);

    k_prep<<<(SS * SS + WK * SS + 255) / 256, 256>>>(Aw, Bw, Ew);     // 0
    k_drive<<<(TT * BB) / 32, 512>>>(U, D);                            // 1
    k_powers<<<SS / 2, 256>>>();                                       // 2
    k_scan_mma<1><<<(CCH - 1) * 2, 256, SM_SCAN_TOT>>>(Aw, out, 0);    // 3 (pass1)
    k_pass2<<<BB / 2, 128>>>(x);                                       // 4
    k_scan_mma<3><<<CCH * 2, 256, SM_SCAN_TOT>>>(Aw, out, dup);        // 5 (pass3)
}